// round 8
// baseline (speedup 1.0000x reference)
#include <cuda_runtime.h>
#include <cuda_fp16.h>
#include <cstdint>

// Problem constants: N=100000, F_IN=512, F_OUT=128, nnz=1.6M each
#define F_OUT  128
#define F_IN   512
#define NMAX   100000
#define CAP    48      // ELL row capacity; P(Poisson(16) >= 48) ~ 1e-10 per node

// ---------- scratch (__device__ globals; allocation-free) ----------
__device__ __half g_base[(size_t)NMAX * F_OUT];        // intermediate [N,128] fp16 (25.6 MB, L2-resident)
__device__ __half g_wh[(size_t)F_IN * F_OUT];          // W in fp16 (128 KB, L1-resident)
__device__ int    d_deg_f[NMAX];
__device__ int    d_deg_a[NMAX];
__device__ int2   d_ell_f[(size_t)NMAX * CAP];         // packed {col, val_bits}, 384B rows (16B-aligned)
__device__ int2   d_ell_a[(size_t)NMAX * CAP];         // packed {src, val_bits}

// ---------- prep: zero degree counters + convert W to fp16, one kernel ----------
__global__ void prep_kernel(const float2* __restrict__ w2, int n) {
    int stride = gridDim.x * blockDim.x;
    int t0 = blockIdx.x * blockDim.x + threadIdx.x;
    for (int i = t0; i < n; i += stride) {
        d_deg_f[i] = 0;
        d_deg_a[i] = 0;
    }
    for (int i = t0; i < (F_IN * F_OUT) / 2; i += stride) {
        float2 f = w2[i];
        reinterpret_cast<__half2*>(g_wh)[i] = __floats2half2_rn(f.x, f.y);
    }
}

__global__ void build_ell_kernel(const int* __restrict__ f_rows,
                                 const int* __restrict__ f_cols,
                                 const float* __restrict__ f_vals, int fn,
                                 const int* __restrict__ a_dst,
                                 const int* __restrict__ a_src,
                                 const float* __restrict__ a_vals, int an) {
    int i = blockIdx.x * blockDim.x + threadIdx.x;
    if (i < fn) {
        int r = f_rows[i];
        int p = atomicAdd(&d_deg_f[r], 1);
        p = min(p, CAP - 1);                           // overflow guard (never hit)
        d_ell_f[(size_t)r * CAP + p] = make_int2(f_cols[i], __float_as_int(f_vals[i]));
    } else if (i < fn + an) {
        int j = i - fn;
        int r = a_dst[j];
        int p = atomicAdd(&d_deg_a[r], 1);
        p = min(p, CAP - 1);
        d_ell_a[(size_t)r * CAP + p] = make_int2(a_src[j], __float_as_int(a_vals[j]));
    }
}

// ---------- gather SpMMs (warp per node, dual edge-chain + pair prefetch) ----------

__device__ __forceinline__ void fma_h2(float4& acc, float v, uint2 u) {
    __half2 h0 = *reinterpret_cast<const __half2*>(&u.x);
    __half2 h1 = *reinterpret_cast<const __half2*>(&u.y);
    float2 f0 = __half22float2(h0);
    float2 f1 = __half22float2(h1);
    acc.x += v * f0.x;  acc.y += v * f0.y;
    acc.z += v * f1.x;  acc.w += v * f1.y;
}

// Shared inner routine: out_vec = sum over ELL row of v_j * table[c_j * 32 + lane]
__device__ __forceinline__ float4 gather_row(const int2* __restrict__ ell, int deg,
                                             const uint2* __restrict__ tp /* table + lane */) {
    float4 accA = make_float4(0.f, 0.f, 0.f, 0.f);
    float4 accB = make_float4(0.f, 0.f, 0.f, 0.f);
    const int4* __restrict__ ell4 = reinterpret_cast<const int4*>(ell);

    int pairs = deg >> 1;          // full pairs
    if (pairs > 0) {
        int4 m = __ldg(ell4);      // edges 0,1: {c0, v0, c1, v1}
        uint2 b0 = __ldg(&tp[(size_t)m.x << 5]);
        uint2 b1 = __ldg(&tp[(size_t)m.z << 5]);
        for (int p = 1; p < pairs; p++) {
            int4 mn = __ldg(&ell4[p]);                 // next pair meta
            uint2 n0 = __ldg(&tp[(size_t)mn.x << 5]);  // two independent gathers
            uint2 n1 = __ldg(&tp[(size_t)mn.z << 5]);
            fma_h2(accA, __int_as_float(m.y), b0);     // consume current pair
            fma_h2(accB, __int_as_float(m.w), b1);
            m = mn;  b0 = n0;  b1 = n1;
        }
        fma_h2(accA, __int_as_float(m.y), b0);
        fma_h2(accB, __int_as_float(m.w), b1);
    }
    if (deg & 1) {                 // odd remainder: one scalar edge
        int2  t = __ldg(&ell[deg - 1]);
        uint2 b = __ldg(&tp[(size_t)t.x << 5]);
        fma_h2(accA, __int_as_float(t.y), b);
    }
    accA.x += accB.x;  accA.y += accB.y;
    accA.z += accB.z;  accA.w += accB.w;
    return accA;
}

// Step 1: base[node, :] = sum_j v_j * W[c_j, :]   (W fp16, 128 KB, L1-resident)
__global__ void __launch_bounds__(256) gemm_feat_kernel(int n) {
    int node = (blockIdx.x * blockDim.x + threadIdx.x) >> 5;
    int lane = threadIdx.x & 31;
    if (node >= n) return;
    int deg = min(d_deg_f[node], CAP);
    const int2* __restrict__ ell = &d_ell_f[(size_t)node * CAP];
    const uint2* __restrict__ wp = reinterpret_cast<const uint2*>(g_wh) + lane;

    float4 acc = gather_row(ell, deg, wp);

    __half2 h0 = __floats2half2_rn(acc.x, acc.y);
    __half2 h1 = __floats2half2_rn(acc.z, acc.w);
    uint2 u;
    u.x = *reinterpret_cast<unsigned*>(&h0);
    u.y = *reinterpret_cast<unsigned*>(&h1);
    reinterpret_cast<uint2*>(g_base)[((size_t)node << 5) + lane] = u;
}

// Step 2: out[node, :] = sum_e v_e * base[src_e, :]  (base 25.6 MB fp16, L2-resident)
__global__ void __launch_bounds__(256) gemm_adj_kernel(float4* __restrict__ out4, int n) {
    int node = (blockIdx.x * blockDim.x + threadIdx.x) >> 5;
    int lane = threadIdx.x & 31;
    if (node >= n) return;
    int deg = min(d_deg_a[node], CAP);
    const int2* __restrict__ ell = &d_ell_a[(size_t)node * CAP];
    const uint2* __restrict__ bp = reinterpret_cast<const uint2*>(g_base) + lane;

    float4 acc = gather_row(ell, deg, bp);
    out4[((size_t)node << 5) + lane] = acc;
}

// Inputs (metadata order):
//   d_in[0]: adj_indices  int32  [2 * N_EDGES]   (dst rows, then src cols)
//   d_in[1]: adj_values   fp32   [N_EDGES]
//   d_in[2]: feat_rows    int32  [FEAT_NNZ]
//   d_in[3]: feat_cols    int32  [FEAT_NNZ]
//   d_in[4]: feat_values  fp32   [FEAT_NNZ]
//   d_in[5]: weight       fp32   [F_IN * F_OUT]
//   d_in[6]: num_nodes    int32  [1]
// Output: fp32 [N, F_OUT]
extern "C" void kernel_launch(void* const* d_in, const int* in_sizes, int n_in,
                              void* d_out, int out_size) {
    const int*   adj_idx  = (const int*)  d_in[0];
    const float* adj_vals = (const float*)d_in[1];
    const int*   f_rows   = (const int*)  d_in[2];
    const int*   f_cols   = (const int*)  d_in[3];
    const float* f_vals   = (const float*)d_in[4];
    const float* weight   = (const float*)d_in[5];
    float*       out      = (float*)d_out;

    int n_edges   = in_sizes[1];
    int feat_nnz  = in_sizes[4];
    int num_nodes = out_size / F_OUT;

    prep_kernel<<<256, 512>>>((const float2*)weight, num_nodes);

    int total = feat_nnz + n_edges;
    build_ell_kernel<<<(total + 255) / 256, 256>>>(f_rows, f_cols, f_vals, feat_nnz,
                                                   adj_idx, adj_idx + n_edges, adj_vals,
                                                   n_edges);

    int warp_blocks = (num_nodes * 32 + 255) / 256;
    gemm_feat_kernel<<<warp_blocks, 256>>>(num_nodes);
    gemm_adj_kernel<<<warp_blocks, 256>>>((float4*)out, num_nodes);
}

// round 9
// speedup vs baseline: 1.0326x; 1.0326x over previous
#include <cuda_runtime.h>
#include <cuda_fp16.h>
#include <cstdint>

// Problem constants: N=100000, F_IN=512, F_OUT=128, nnz=1.6M each
#define F_OUT  128
#define F_IN   512
#define NMAX   100000
#define CAP    64      // ELL row capacity; degrees ~Poisson(16), P(deg>=64) ~ 1e-18

// ---------- scratch (__device__ globals; allocation-free) ----------
__device__ __half g_base[(size_t)NMAX * F_OUT];        // intermediate [N,128] fp16 (25.6 MB, L2-resident)
__device__ __half g_wh[(size_t)F_IN * F_OUT];          // W in fp16 (128 KB, L1-resident)
__device__ int    d_deg_f[NMAX];
__device__ int    d_deg_a[NMAX];
__device__ int2   d_ell_f[(size_t)NMAX * CAP];         // packed {col, val_bits}
__device__ int2   d_ell_a[(size_t)NMAX * CAP];         // packed {src, val_bits}

// ---------- prep: zero degree counters + convert W to fp16, one kernel ----------
__global__ void prep_kernel(const float2* __restrict__ w2, int n) {
    int stride = gridDim.x * blockDim.x;
    int t0 = blockIdx.x * blockDim.x + threadIdx.x;
    for (int i = t0; i < n; i += stride) {
        d_deg_f[i] = 0;
        d_deg_a[i] = 0;
    }
    for (int i = t0; i < (F_IN * F_OUT) / 2; i += stride) {
        float2 f = w2[i];
        reinterpret_cast<__half2*>(g_wh)[i] = __floats2half2_rn(f.x, f.y);
    }
}

__global__ void build_ell_kernel(const int* __restrict__ f_rows,
                                 const int* __restrict__ f_cols,
                                 const float* __restrict__ f_vals, int fn,
                                 const int* __restrict__ a_dst,
                                 const int* __restrict__ a_src,
                                 const float* __restrict__ a_vals, int an) {
    int i = blockIdx.x * blockDim.x + threadIdx.x;
    if (i < fn) {
        int r = f_rows[i];
        int p = atomicAdd(&d_deg_f[r], 1);
        p = min(p, CAP - 1);                           // overflow guard (never hit)
        d_ell_f[(size_t)r * CAP + p] = make_int2(f_cols[i], __float_as_int(f_vals[i]));
    } else if (i < fn + an) {
        int j = i - fn;
        int r = a_dst[j];
        int p = atomicAdd(&d_deg_a[r], 1);
        p = min(p, CAP - 1);
        d_ell_a[(size_t)r * CAP + p] = make_int2(a_src[j], __float_as_int(a_vals[j]));
    }
}

// ---------- gather SpMMs: warp per 2 nodes, two independent depth-1 chains ----------

__device__ __forceinline__ void fma_h2(float4& acc, float v, uint2 u) {
    __half2 h0 = *reinterpret_cast<const __half2*>(&u.x);
    __half2 h1 = *reinterpret_cast<const __half2*>(&u.y);
    float2 f0 = __half22float2(h0);
    float2 f1 = __half22float2(h1);
    acc.x += v * f0.x;  acc.y += v * f0.y;
    acc.z += v * f1.x;  acc.w += v * f1.y;
}

// Two interleaved R7-style prefetch chains (one per node), shared table pointer.
__device__ __forceinline__ void gather2(const int2* __restrict__ ellA, int dA,
                                        const int2* __restrict__ ellB, int dB,
                                        const uint2* __restrict__ tp /* table + lane */,
                                        float4& accA, float4& accB) {
    int dmin = min(dA, dB);
    if (dmin > 0) {
        int2  tA = __ldg(ellA),                tB = __ldg(ellB);
        uint2 bA = __ldg(&tp[(size_t)tA.x << 5]);
        uint2 bB = __ldg(&tp[(size_t)tB.x << 5]);
        for (int j = 1; j < dmin; j++) {
            int2  tAn = __ldg(&ellA[j]);
            int2  tBn = __ldg(&ellB[j]);
            uint2 bAn = __ldg(&tp[(size_t)tAn.x << 5]);
            uint2 bBn = __ldg(&tp[(size_t)tBn.x << 5]);
            fma_h2(accA, __int_as_float(tA.y), bA);
            fma_h2(accB, __int_as_float(tB.y), bB);
            tA = tAn;  bA = bAn;  tB = tBn;  bB = bBn;
        }
        fma_h2(accA, __int_as_float(tA.y), bA);
        fma_h2(accB, __int_as_float(tB.y), bB);
    }
    for (int j = dmin; j < dA; j++) {               // tail of longer row (E[len] ~ 4.5)
        int2  t = __ldg(&ellA[j]);
        uint2 b = __ldg(&tp[(size_t)t.x << 5]);
        fma_h2(accA, __int_as_float(t.y), b);
    }
    for (int j = dmin; j < dB; j++) {
        int2  t = __ldg(&ellB[j]);
        uint2 b = __ldg(&tp[(size_t)t.x << 5]);
        fma_h2(accB, __int_as_float(t.y), b);
    }
}

// Step 1: base[node, :] = sum_j v_j * W[c_j, :]   (W fp16, 128 KB, L1-resident)
__global__ void __launch_bounds__(256) gemm_feat_kernel(int n) {
    int w    = (blockIdx.x * blockDim.x + threadIdx.x) >> 5;
    int lane = threadIdx.x & 31;
    int n0 = w * 2;
    if (n0 >= n) return;
    int n1 = n0 + 1;
    int dA = min(d_deg_f[n0], CAP);
    int dB = (n1 < n) ? min(d_deg_f[n1], CAP) : 0;
    const int2* __restrict__ ellA = &d_ell_f[(size_t)n0 * CAP];
    const int2* __restrict__ ellB = &d_ell_f[(size_t)min(n1, n - 1) * CAP];
    const uint2* __restrict__ wp = reinterpret_cast<const uint2*>(g_wh) + lane;

    float4 accA = make_float4(0.f, 0.f, 0.f, 0.f);
    float4 accB = make_float4(0.f, 0.f, 0.f, 0.f);
    gather2(ellA, dA, ellB, dB, wp, accA, accB);

    uint2* __restrict__ bout = reinterpret_cast<uint2*>(g_base);
    {
        __half2 h0 = __floats2half2_rn(accA.x, accA.y);
        __half2 h1 = __floats2half2_rn(accA.z, accA.w);
        uint2 u;
        u.x = *reinterpret_cast<unsigned*>(&h0);
        u.y = *reinterpret_cast<unsigned*>(&h1);
        bout[((size_t)n0 << 5) + lane] = u;
    }
    if (n1 < n) {
        __half2 h0 = __floats2half2_rn(accB.x, accB.y);
        __half2 h1 = __floats2half2_rn(accB.z, accB.w);
        uint2 u;
        u.x = *reinterpret_cast<unsigned*>(&h0);
        u.y = *reinterpret_cast<unsigned*>(&h1);
        bout[((size_t)n1 << 5) + lane] = u;
    }
}

// Step 2: out[node, :] = sum_e v_e * base[src_e, :]  (base 25.6 MB fp16, L2-resident)
__global__ void __launch_bounds__(256) gemm_adj_kernel(float4* __restrict__ out4, int n) {
    int w    = (blockIdx.x * blockDim.x + threadIdx.x) >> 5;
    int lane = threadIdx.x & 31;
    int n0 = w * 2;
    if (n0 >= n) return;
    int n1 = n0 + 1;
    int dA = min(d_deg_a[n0], CAP);
    int dB = (n1 < n) ? min(d_deg_a[n1], CAP) : 0;
    const int2* __restrict__ ellA = &d_ell_a[(size_t)n0 * CAP];
    const int2* __restrict__ ellB = &d_ell_a[(size_t)min(n1, n - 1) * CAP];
    const uint2* __restrict__ bp = reinterpret_cast<const uint2*>(g_base) + lane;

    float4 accA = make_float4(0.f, 0.f, 0.f, 0.f);
    float4 accB = make_float4(0.f, 0.f, 0.f, 0.f);
    gather2(ellA, dA, ellB, dB, bp, accA, accB);

    out4[((size_t)n0 << 5) + lane] = accA;
    if (n1 < n) out4[((size_t)n1 << 5) + lane] = accB;
}

// Inputs (metadata order):
//   d_in[0]: adj_indices  int32  [2 * N_EDGES]   (dst rows, then src cols)
//   d_in[1]: adj_values   fp32   [N_EDGES]
//   d_in[2]: feat_rows    int32  [FEAT_NNZ]
//   d_in[3]: feat_cols    int32  [FEAT_NNZ]
//   d_in[4]: feat_values  fp32   [FEAT_NNZ]
//   d_in[5]: weight       fp32   [F_IN * F_OUT]
//   d_in[6]: num_nodes    int32  [1]
// Output: fp32 [N, F_OUT]
extern "C" void kernel_launch(void* const* d_in, const int* in_sizes, int n_in,
                              void* d_out, int out_size) {
    const int*   adj_idx  = (const int*)  d_in[0];
    const float* adj_vals = (const float*)d_in[1];
    const int*   f_rows   = (const int*)  d_in[2];
    const int*   f_cols   = (const int*)  d_in[3];
    const float* f_vals   = (const float*)d_in[4];
    const float* weight   = (const float*)d_in[5];
    float*       out      = (float*)d_out;

    int n_edges   = in_sizes[1];
    int feat_nnz  = in_sizes[4];
    int num_nodes = out_size / F_OUT;

    prep_kernel<<<256, 512>>>((const float2*)weight, num_nodes);

    int total = feat_nnz + n_edges;
    build_ell_kernel<<<(total + 255) / 256, 256>>>(f_rows, f_cols, f_vals, feat_nnz,
                                                   adj_idx, adj_idx + n_edges, adj_vals,
                                                   n_edges);

    int nwarps = (num_nodes + 1) / 2;
    int warp_blocks = (nwarps * 32 + 255) / 256;
    gemm_feat_kernel<<<warp_blocks, 256>>>(num_nodes);
    gemm_adj_kernel<<<warp_blocks, 256>>>((float4*)out, num_nodes);
}

// round 10
// speedup vs baseline: 1.0818x; 1.0476x over previous
#include <cuda_runtime.h>
#include <cuda_fp16.h>
#include <cstdint>

// Problem constants: N=100000, F_IN=512, F_OUT=128, nnz=1.6M each
#define F_OUT  128
#define F_IN   512
#define NMAX   100000
#define CAP    48      // ELL row capacity; P(Poisson(16) >= 48) ~ 1e-10/node (validated in R8)

// ---------- scratch (__device__ globals; allocation-free) ----------
__device__ __half g_base[(size_t)NMAX * F_OUT];        // intermediate [N,128] fp16 (25.6 MB, L2-resident)
__device__ __half g_wh[(size_t)F_IN * F_OUT];          // W in fp16 (128 KB, L1-resident)
__device__ int    d_deg_f[NMAX];
__device__ int    d_deg_a[NMAX];
__device__ int2   d_ell_f[(size_t)NMAX * CAP];         // packed {col, val_bits} (38.4 MB)
__device__ int2   d_ell_a[(size_t)NMAX * CAP];         // packed {src, val_bits} (38.4 MB)

// ---------- K1 prep: zero degree counters + convert W to fp16 ----------
__global__ void prep_kernel(const float2* __restrict__ w2, int n) {
    int stride = gridDim.x * blockDim.x;
    int t0 = blockIdx.x * blockDim.x + threadIdx.x;
    for (int i = t0; i < n; i += stride) {
        d_deg_f[i] = 0;
        d_deg_a[i] = 0;
    }
    for (int i = t0; i < (F_IN * F_OUT) / 2; i += stride) {
        float2 f = w2[i];
        reinterpret_cast<__half2*>(g_wh)[i] = __floats2half2_rn(f.x, f.y);
    }
}

// ---------- K2: build feature ELL only ----------
__global__ void build_f_kernel(const int* __restrict__ f_rows,
                               const int* __restrict__ f_cols,
                               const float* __restrict__ f_vals, int fn) {
    int i = blockIdx.x * blockDim.x + threadIdx.x;
    if (i >= fn) return;
    int r = f_rows[i];
    int p = atomicAdd(&d_deg_f[r], 1);
    p = min(p, CAP - 1);                               // overflow guard (never hit)
    d_ell_f[(size_t)r * CAP + p] = make_int2(f_cols[i], __float_as_int(f_vals[i]));
}

// ---------- shared fp16 FMA helper ----------
__device__ __forceinline__ void fma_h2(float4& acc, float v, uint2 u) {
    __half2 h0 = *reinterpret_cast<const __half2*>(&u.x);
    __half2 h1 = *reinterpret_cast<const __half2*>(&u.y);
    float2 f0 = __half22float2(h0);
    float2 f1 = __half22float2(h1);
    acc.x += v * f0.x;  acc.y += v * f0.y;
    acc.z += v * f1.x;  acc.w += v * f1.y;
}

// ---------- K3 fused: adjacency ELL build (independent) || feat gather ----------
// Blocks [0, build_blocks): grid-stride build of d_ell_a.
// Blocks [build_blocks, ...): R7-style warp-per-node feat gather (depth-1 prefetch).
__global__ void __launch_bounds__(256) fused_feat_builda_kernel(
        const int* __restrict__ a_dst,
        const int* __restrict__ a_src,
        const float* __restrict__ a_vals, int an,
        int n, int build_blocks) {
    if (blockIdx.x < build_blocks) {
        int stride = build_blocks * blockDim.x;
        for (int i = blockIdx.x * blockDim.x + threadIdx.x; i < an; i += stride) {
            int r = a_dst[i];
            int p = atomicAdd(&d_deg_a[r], 1);
            p = min(p, CAP - 1);
            d_ell_a[(size_t)r * CAP + p] = make_int2(a_src[i], __float_as_int(a_vals[i]));
        }
        return;
    }

    // ---- feat gather: base[node,:] = sum_j v_j * W[c_j,:]  (W fp16, L1-resident) ----
    int node = (((blockIdx.x - build_blocks) * blockDim.x) + threadIdx.x) >> 5;
    int lane = threadIdx.x & 31;
    if (node >= n) return;
    int deg = min(d_deg_f[node], CAP);
    const int2* __restrict__ ell = &d_ell_f[(size_t)node * CAP];
    const uint2* __restrict__ wp = reinterpret_cast<const uint2*>(g_wh) + lane;

    float4 acc = make_float4(0.f, 0.f, 0.f, 0.f);
    if (deg > 0) {
        int2  t = __ldg(ell);
        uint2 w = __ldg(&wp[(size_t)t.x << 5]);
        for (int j = 1; j < deg; j++) {
            int2  tn = __ldg(&ell[j]);                  // prefetch next edge
            uint2 wn = __ldg(&wp[(size_t)tn.x << 5]);
            fma_h2(acc, __int_as_float(t.y), w);        // consume current
            t = tn;  w = wn;
        }
        fma_h2(acc, __int_as_float(t.y), w);
    }
    __half2 h0 = __floats2half2_rn(acc.x, acc.y);
    __half2 h1 = __floats2half2_rn(acc.z, acc.w);
    uint2 u;
    u.x = *reinterpret_cast<unsigned*>(&h0);
    u.y = *reinterpret_cast<unsigned*>(&h1);
    reinterpret_cast<uint2*>(g_base)[((size_t)node << 5) + lane] = u;
}

// ---------- K4: adj gather (exact R7 structure) ----------
__global__ void __launch_bounds__(256) gemm_adj_kernel(float4* __restrict__ out4, int n) {
    int node = (blockIdx.x * blockDim.x + threadIdx.x) >> 5;
    int lane = threadIdx.x & 31;
    if (node >= n) return;
    int deg = min(d_deg_a[node], CAP);
    const int2* __restrict__ ell = &d_ell_a[(size_t)node * CAP];
    const uint2* __restrict__ bp = reinterpret_cast<const uint2*>(g_base) + lane;

    float4 acc = make_float4(0.f, 0.f, 0.f, 0.f);
    if (deg > 0) {
        int2  t = __ldg(ell);
        uint2 b = __ldg(&bp[(size_t)t.x << 5]);
        for (int j = 1; j < deg; j++) {
            int2  tn = __ldg(&ell[j]);                  // prefetch next edge
            uint2 bn = __ldg(&bp[(size_t)tn.x << 5]);
            fma_h2(acc, __int_as_float(t.y), b);        // consume current
            t = tn;  b = bn;
        }
        fma_h2(acc, __int_as_float(t.y), b);
    }
    out4[((size_t)node << 5) + lane] = acc;
}

// Inputs (metadata order):
//   d_in[0]: adj_indices  int32  [2 * N_EDGES]   (dst rows, then src cols)
//   d_in[1]: adj_values   fp32   [N_EDGES]
//   d_in[2]: feat_rows    int32  [FEAT_NNZ]
//   d_in[3]: feat_cols    int32  [FEAT_NNZ]
//   d_in[4]: feat_values  fp32   [FEAT_NNZ]
//   d_in[5]: weight       fp32   [F_IN * F_OUT]
//   d_in[6]: num_nodes    int32  [1]
// Output: fp32 [N, F_OUT]
extern "C" void kernel_launch(void* const* d_in, const int* in_sizes, int n_in,
                              void* d_out, int out_size) {
    const int*   adj_idx  = (const int*)  d_in[0];
    const float* adj_vals = (const float*)d_in[1];
    const int*   f_rows   = (const int*)  d_in[2];
    const int*   f_cols   = (const int*)  d_in[3];
    const float* f_vals   = (const float*)d_in[4];
    const float* weight   = (const float*)d_in[5];
    float*       out      = (float*)d_out;

    int n_edges   = in_sizes[1];
    int feat_nnz  = in_sizes[4];
    int num_nodes = out_size / F_OUT;

    // K1: prep
    prep_kernel<<<256, 512>>>((const float2*)weight, num_nodes);

    // K2: build feature ELL
    build_f_kernel<<<(feat_nnz + 255) / 256, 256>>>(f_rows, f_cols, f_vals, feat_nnz);

    // K3: feat gather overlapped with adjacency ELL build
    const int BUILD_BLOCKS = 2000;                     // 512K threads grid-striding 1.6M edges
    int feat_blocks = (num_nodes * 32 + 255) / 256;    // warp per node
    fused_feat_builda_kernel<<<BUILD_BLOCKS + feat_blocks, 256>>>(
        adj_idx, adj_idx + n_edges, adj_vals, n_edges, num_nodes, BUILD_BLOCKS);

    // K4: adj gather
    int warp_blocks = (num_nodes * 32 + 255) / 256;
    gemm_adj_kernel<<<warp_blocks, 256>>>((float4*)out, num_nodes);
}

// round 11
// speedup vs baseline: 1.1688x; 1.0804x over previous
#include <cuda_runtime.h>
#include <cuda_fp16.h>
#include <cstdint>

// Problem constants: N=100000, F_IN=512, F_OUT=128, nnz=1.6M each
#define F_OUT  128
#define F_IN   512
#define NMAX   100000
#define CAP    48      // ELL row capacity; P(Poisson(16) >= 48) ~ 1e-10/node (validated R8/R10)

// ---------- scratch (__device__ globals; allocation-free) ----------
__device__ __half g_base[(size_t)NMAX * F_OUT];        // intermediate [N,128] fp16 (25.6 MB, L2-resident)
__device__ __half g_wh[(size_t)F_IN * F_OUT];          // W in fp16 (128 KB, L1-resident)
__device__ int    d_deg_f[NMAX];
__device__ int    d_deg_a[NMAX];
__device__ int2   d_ell_f[(size_t)NMAX * CAP];         // packed {col, val_bits} (38.4 MB)
__device__ int2   d_ell_a[(size_t)NMAX * CAP];         // packed {src, val_bits} (38.4 MB)

// ---------- K1 prep: zero degree counters + convert W to fp16 ----------
__global__ void prep_kernel(const float2* __restrict__ w2, int n) {
    int stride = gridDim.x * blockDim.x;
    int t0 = blockIdx.x * blockDim.x + threadIdx.x;
    for (int i = t0; i < n; i += stride) {
        d_deg_f[i] = 0;
        d_deg_a[i] = 0;
    }
    for (int i = t0; i < (F_IN * F_OUT) / 2; i += stride) {
        float2 f = w2[i];
        reinterpret_cast<__half2*>(g_wh)[i] = __floats2half2_rn(f.x, f.y);
    }
}

// ---------- K2: build feature ELL only ----------
__global__ void build_f_kernel(const int* __restrict__ f_rows,
                               const int* __restrict__ f_cols,
                               const float* __restrict__ f_vals, int fn) {
    int i = blockIdx.x * blockDim.x + threadIdx.x;
    if (i >= fn) return;
    int r = f_rows[i];
    int p = atomicAdd(&d_deg_f[r], 1);
    p = min(p, CAP - 1);                               // overflow guard (never hit)
    d_ell_f[(size_t)r * CAP + p] = make_int2(f_cols[i], __float_as_int(f_vals[i]));
}

// ---------- shared fp16 FMA helper ----------
__device__ __forceinline__ void fma_h2(float4& acc, float v, uint2 u) {
    __half2 h0 = *reinterpret_cast<const __half2*>(&u.x);
    __half2 h1 = *reinterpret_cast<const __half2*>(&u.y);
    float2 f0 = __half22float2(h0);
    float2 f1 = __half22float2(h1);
    acc.x += v * f0.x;  acc.y += v * f0.y;
    acc.z += v * f1.x;  acc.w += v * f1.y;
}

// ---------- K3 fused: feat gather || adjacency ELL build, roles INTERLEAVED ----------
// Builder iff blockIdx.x % 8 == 7 -> every scheduling wave mixes ~1/8 builders with
// ~7/8 feat blocks, so the two latency-bound streams genuinely co-execute.
__global__ void __launch_bounds__(256) fused_feat_builda_kernel(
        const int* __restrict__ a_dst,
        const int* __restrict__ a_src,
        const float* __restrict__ a_vals, int an,
        int n, int n_builders) {
    unsigned x = blockIdx.x;
    if ((x & 7u) == 7u) {
        // ---- builder role: grid-stride over adjacency edges ----
        int rank = x >> 3;                              // 0 .. n_builders-1
        int stride = n_builders * blockDim.x;
        for (int i = rank * blockDim.x + threadIdx.x; i < an; i += stride) {
            int r = a_dst[i];
            int p = atomicAdd(&d_deg_a[r], 1);
            p = min(p, CAP - 1);
            d_ell_a[(size_t)r * CAP + p] = make_int2(a_src[i], __float_as_int(a_vals[i]));
        }
        return;
    }

    // ---- feat role: base[node,:] = sum_j v_j * W[c_j,:]  (W fp16, L1-resident) ----
    int fblk = (int)(x - ((x + 1) >> 3));               // # feat blocks before x
    int node = ((fblk * blockDim.x) + threadIdx.x) >> 5;
    int lane = threadIdx.x & 31;
    if (node >= n) return;
    int deg = min(d_deg_f[node], CAP);
    const int2* __restrict__ ell = &d_ell_f[(size_t)node * CAP];
    const uint2* __restrict__ wp = reinterpret_cast<const uint2*>(g_wh) + lane;

    float4 acc = make_float4(0.f, 0.f, 0.f, 0.f);
    if (deg > 0) {
        int2  t = __ldg(ell);
        uint2 w = __ldg(&wp[(size_t)t.x << 5]);
        for (int j = 1; j < deg; j++) {
            int2  tn = __ldg(&ell[j]);                  // prefetch next edge
            uint2 wn = __ldg(&wp[(size_t)tn.x << 5]);
            fma_h2(acc, __int_as_float(t.y), w);        // consume current
            t = tn;  w = wn;
        }
        fma_h2(acc, __int_as_float(t.y), w);
    }
    __half2 h0 = __floats2half2_rn(acc.x, acc.y);
    __half2 h1 = __floats2half2_rn(acc.z, acc.w);
    uint2 u;
    u.x = *reinterpret_cast<unsigned*>(&h0);
    u.y = *reinterpret_cast<unsigned*>(&h1);
    reinterpret_cast<uint2*>(g_base)[((size_t)node << 5) + lane] = u;
}

// ---------- K4: adj gather (exact R7 structure) ----------
__global__ void __launch_bounds__(256) gemm_adj_kernel(float4* __restrict__ out4, int n) {
    int node = (blockIdx.x * blockDim.x + threadIdx.x) >> 5;
    int lane = threadIdx.x & 31;
    if (node >= n) return;
    int deg = min(d_deg_a[node], CAP);
    const int2* __restrict__ ell = &d_ell_a[(size_t)node * CAP];
    const uint2* __restrict__ bp = reinterpret_cast<const uint2*>(g_base) + lane;

    float4 acc = make_float4(0.f, 0.f, 0.f, 0.f);
    if (deg > 0) {
        int2  t = __ldg(ell);
        uint2 b = __ldg(&bp[(size_t)t.x << 5]);
        for (int j = 1; j < deg; j++) {
            int2  tn = __ldg(&ell[j]);                  // prefetch next edge
            uint2 bn = __ldg(&bp[(size_t)tn.x << 5]);
            fma_h2(acc, __int_as_float(t.y), b);        // consume current
            t = tn;  b = bn;
        }
        fma_h2(acc, __int_as_float(t.y), b);
    }
    out4[((size_t)node << 5) + lane] = acc;
}

// Inputs (metadata order):
//   d_in[0]: adj_indices  int32  [2 * N_EDGES]   (dst rows, then src cols)
//   d_in[1]: adj_values   fp32   [N_EDGES]
//   d_in[2]: feat_rows    int32  [FEAT_NNZ]
//   d_in[3]: feat_cols    int32  [FEAT_NNZ]
//   d_in[4]: feat_values  fp32   [FEAT_NNZ]
//   d_in[5]: weight       fp32   [F_IN * F_OUT]
//   d_in[6]: num_nodes    int32  [1]
// Output: fp32 [N, F_OUT]
extern "C" void kernel_launch(void* const* d_in, const int* in_sizes, int n_in,
                              void* d_out, int out_size) {
    const int*   adj_idx  = (const int*)  d_in[0];
    const float* adj_vals = (const float*)d_in[1];
    const int*   f_rows   = (const int*)  d_in[2];
    const int*   f_cols   = (const int*)  d_in[3];
    const float* f_vals   = (const float*)d_in[4];
    const float* weight   = (const float*)d_in[5];
    float*       out      = (float*)d_out;

    int n_edges   = in_sizes[1];
    int feat_nnz  = in_sizes[4];
    int num_nodes = out_size / F_OUT;

    // K1: prep
    prep_kernel<<<256, 512>>>((const float2*)weight, num_nodes);

    // K2: build feature ELL
    build_f_kernel<<<(feat_nnz + 255) / 256, 256>>>(f_rows, f_cols, f_vals, feat_nnz);

    // K3: feat gather with interleaved adjacency-build blocks (every 8th block)
    int feat_blocks = (num_nodes * 32 + 255) / 256;     // 12500 needed
    // Grid G with builders at x%8==7: feat count = G - floor((G+1)/8) (approx G*7/8).
    // Pick G so feat count >= feat_blocks.
    int G = ((feat_blocks * 8) + 6) / 7 + 8;            // ~14294
    int n_builders = (G + 1) >> 3;                      // count of x in [0,G) with x%8==7 (safe upper)
    // Recompute exactly: x%8==7 for x<G -> count = (G >> 3) + ((G & 7) == 0 ? 0 : ((G & 7) > 7 ? 1 : 0));
    n_builders = G >> 3;                                // floor(G/8); pattern 7,15,... all < G when G%8>=0
    if ((G & 7) == 0) n_builders = G >> 3;              // exact for our G
    fused_feat_builda_kernel<<<G, 256>>>(
        adj_idx, adj_idx + n_edges, adj_vals, n_edges, num_nodes, n_builders);

    // K4: adj gather
    int warp_blocks = (num_nodes * 32 + 255) / 256;
    gemm_adj_kernel<<<warp_blocks, 256>>>((float4*)out, num_nodes);
}